// round 2
// baseline (speedup 1.0000x reference)
#include <cuda_runtime.h>

#define S_LEN 16384
#define HL 48
#define HR 24
#define GATES 192

__device__ float g_xw0[(size_t)S_LEN * GATES];
__device__ float g_xwb[4][(size_t)S_LEN * GATES];
__device__ float g_hb[5][(size_t)S_LEN * HL];
__device__ float g_r0[(size_t)S_LEN * HR];
__device__ int   g_cnt[16];

typedef unsigned long long u64;

__device__ __forceinline__ u64 pack2(float x, float y) {
    u64 r; asm("mov.b64 %0, {%1, %2};" : "=l"(r) : "f"(x), "f"(y)); return r;
}
__device__ __forceinline__ void unpack2(u64 v, float &x, float &y) {
    asm("mov.b64 {%0, %1}, %2;" : "=f"(x), "=f"(y) : "l"(v));
}
__device__ __forceinline__ u64 ffma2(u64 a, u64 b, u64 c) {
    u64 d; asm("fma.rn.f32x2 %0, %1, %2, %3;" : "=l"(d) : "l"(a), "l"(b), "l"(c)); return d;
}
__device__ __forceinline__ int ld_acq(const int *p) {
    int v; asm volatile("ld.acquire.gpu.global.b32 %0, [%1];" : "=r"(v) : "l"(p)); return v;
}
__device__ __forceinline__ void st_rel(int *p, int v) {
    asm volatile("st.release.gpu.global.b32 [%0], %1;" :: "l"(p), "r"(v));
}
// a=1: sigmoid; a=2: tanh = 2*sigmoid(2x)-1
__device__ __forceinline__ float actf(float x, float a) {
    return __fdividef(a, 1.f + __expf(-a * x)) - (a - 1.f);
}

// ---------------- front: fc1 -> relu -> fc2 -> relu -> xw0 ----------------
__global__ void __launch_bounds__(128) front_kernel(
    const float* __restrict__ x,
    const float* __restrict__ fc1W, const float* __restrict__ fc1b,
    const float* __restrict__ fc2W, const float* __restrict__ fc2b,
    const float* __restrict__ Wih0,
    const float* __restrict__ bih0, const float* __restrict__ bhh0)
{
    __shared__ float s1W[120], s1b[20], s2W[400], s2b[20], s0W[3840], s0b[192];
    const int tid = threadIdx.x;
    for (int i = tid; i < 120; i += 128) s1W[i] = fc1W[i];
    for (int i = tid; i < 400; i += 128) s2W[i] = fc2W[i];
    for (int i = tid; i < 3840; i += 128) s0W[i] = Wih0[i];
    for (int i = tid; i < 192; i += 128) s0b[i] = bih0[i] + bhh0[i];
    if (tid < 20) { s1b[tid] = fc1b[tid]; s2b[tid] = fc2b[tid]; }
    if (blockIdx.x == 0 && tid < 16) g_cnt[tid] = 0;
    __syncthreads();

    const int t = blockIdx.x * 128 + tid;
    float xin[6];
#pragma unroll
    for (int i = 0; i < 6; i++) xin[i] = x[t * 6 + i];
    float h1[20];
#pragma unroll
    for (int j = 0; j < 20; j++) {
        float s = s1b[j];
#pragma unroll
        for (int i = 0; i < 6; i++) s += xin[i] * s1W[j * 6 + i];
        h1[j] = fmaxf(s, 0.f);
    }
    float h2[20];
#pragma unroll
    for (int j = 0; j < 20; j++) {
        float s = s2b[j];
#pragma unroll
        for (int i = 0; i < 20; i++) s += h1[i] * s2W[j * 20 + i];
        h2[j] = fmaxf(s, 0.f);
    }
    float* dst = g_xw0 + (size_t)t * GATES;
    for (int j = 0; j < GATES; j += 2) {
        float s0 = s0b[j], s1 = s0b[j + 1];
#pragma unroll
        for (int k = 0; k < 20; k++) {
            float hv = h2[k];
            s0 += hv * s0W[j * 20 + k];
            s1 += hv * s0W[(j + 1) * 20 + k];
        }
        *(float2*)(dst + j) = make_float2(s0, s1);
    }
}

// ---------------- LSTM recurrence stage ----------------
__device__ void lstm_rec(const float* __restrict__ Whh, const float* __restrict__ xwsrc,
                         const int* upcnt, float* __restrict__ hout, int* mycnt)
{
    __shared__ u64 sh_xw[4][96];
    __shared__ float sh_gact[GATES];
    __shared__ u64 sh_hd[HL];
    const int tid = threadIdx.x;
    u64 w[48];
    float c = 0.f, av = 1.f;
    if (tid < 96) {
        const float* r0 = Whh + (2 * tid) * HL;
        const float* r1 = Whh + (2 * tid + 1) * HL;
#pragma unroll
        for (int k = 0; k < 48; k++) w[k] = pack2(r0[k], r1[k]);
        av = (tid >= 48 && tid < 72) ? 2.f : 1.f;
    }
    if (tid < HL) sh_hd[tid] = 0ULL;

    int avail = 0;
    if (tid >= 96) {
        int lane = tid - 96;
        for (int ft = 0; ft < 2; ft++) {
            if (upcnt) while (avail < ft + 1) avail = ld_acq(upcnt);
            const float* src = xwsrc + (size_t)ft * GATES;
            float* dst = (float*)(&sh_xw[ft][0]);
#pragma unroll
            for (int r = 0; r < 6; r++) dst[r * 32 + lane] = src[r * 32 + lane];
        }
    }
    __syncthreads();

    for (int t = 0; t < S_LEN; t++) {
        if (tid < 96) {
            u64 a0 = sh_xw[t & 3][tid], a1 = 0, a2 = 0, a3 = 0;
#pragma unroll
            for (int k = 0; k < 48; k += 4) {
                a0 = ffma2(sh_hd[k], w[k], a0);
                a1 = ffma2(sh_hd[k + 1], w[k + 1], a1);
                a2 = ffma2(sh_hd[k + 2], w[k + 2], a2);
                a3 = ffma2(sh_hd[k + 3], w[k + 3], a3);
            }
            float x0, y0, x1, y1, x2, y2, x3, y3;
            unpack2(a0, x0, y0); unpack2(a1, x1, y1);
            unpack2(a2, x2, y2); unpack2(a3, x3, y3);
            float gx = (x0 + x1) + (x2 + x3);
            float gy = (y0 + y1) + (y2 + y3);
            gx = actf(gx, av); gy = actf(gy, av);
            *(float2*)(&sh_gact[2 * tid]) = make_float2(gx, gy);
        } else {
            int lane = tid - 96, ft = t + 2;
            if (ft < S_LEN) {
                if (upcnt) while (avail < ft + 1) avail = ld_acq(upcnt);
                const float* src = xwsrc + (size_t)ft * GATES;
                float* dst = (float*)(&sh_xw[ft & 3][0]);
#pragma unroll
                for (int r = 0; r < 6; r++) dst[r * 32 + lane] = src[r * 32 + lane];
            }
        }
        __syncthreads();
        if (tid < HL) {
            float gi = sh_gact[tid], gf = sh_gact[HL + tid];
            float gg = sh_gact[2 * HL + tid], go = sh_gact[3 * HL + tid];
            c = gf * c + gi * gg;
            float h = go * actf(c, 2.f);
            sh_hd[tid] = pack2(h, h);
            hout[(size_t)t * HL + tid] = h;
        }
        __syncthreads();
        if (tid == 0) st_rel(mycnt, t + 1);
    }
}

// ---------------- feedforward xw stage for LSTM layers 1..4 ----------------
__device__ void xw_stage(const float* __restrict__ Wih, const float* __restrict__ bih,
                         const float* __restrict__ bhh, const float* __restrict__ hin,
                         const int* upcnt, float* __restrict__ xwout, int* mycnt)
{
    __shared__ u64 sh_h[4][HL];
    const int tid = threadIdx.x;
    u64 w[48], bias = 0ULL;
    if (tid < 96) {
        const float* r0 = Wih + (2 * tid) * HL;
        const float* r1 = Wih + (2 * tid + 1) * HL;
#pragma unroll
        for (int k = 0; k < 48; k++) w[k] = pack2(r0[k], r1[k]);
        bias = pack2(bih[2 * tid] + bhh[2 * tid], bih[2 * tid + 1] + bhh[2 * tid + 1]);
    }
    int avail = 0;
    if (tid >= 96) {
        int lane = tid - 96;
        for (int ft = 0; ft < 2; ft++) {
            while (avail < ft + 1) avail = ld_acq(upcnt);
            const float* src = hin + (size_t)ft * HL;
            float v = src[lane]; sh_h[ft][lane] = pack2(v, v);
            if (lane < 16) { float v2 = src[32 + lane]; sh_h[ft][32 + lane] = pack2(v2, v2); }
        }
    }
    __syncthreads();
    for (int t = 0; t < S_LEN; t++) {
        if (tid < 96) {
            const u64* hs = sh_h[t & 3];
            u64 a0 = bias, a1 = 0, a2 = 0, a3 = 0;
#pragma unroll
            for (int k = 0; k < 48; k += 4) {
                a0 = ffma2(hs[k], w[k], a0);
                a1 = ffma2(hs[k + 1], w[k + 1], a1);
                a2 = ffma2(hs[k + 2], w[k + 2], a2);
                a3 = ffma2(hs[k + 3], w[k + 3], a3);
            }
            float x0, y0, x1, y1, x2, y2, x3, y3;
            unpack2(a0, x0, y0); unpack2(a1, x1, y1);
            unpack2(a2, x2, y2); unpack2(a3, x3, y3);
            *(float2*)(&xwout[(size_t)t * GATES + 2 * tid]) =
                make_float2((x0 + x1) + (x2 + x3), (y0 + y1) + (y2 + y3));
        } else {
            int lane = tid - 96, ft = t + 2;
            if (ft < S_LEN) {
                while (avail < ft + 1) avail = ld_acq(upcnt);
                const float* src = hin + (size_t)ft * HL;
                float v = src[lane]; sh_h[ft & 3][lane] = pack2(v, v);
                if (lane < 16) { float v2 = src[32 + lane]; sh_h[ft & 3][32 + lane] = pack2(v2, v2); }
            }
        }
        __syncthreads();
        if (tid == 0) st_rel(mycnt, t + 1);
    }
}

// ---------------- RNN0: 48 -> 24 ----------------
__device__ void rnn0_stage(const float* __restrict__ Wih, const float* __restrict__ Whh,
                           const float* __restrict__ bih, const float* __restrict__ bhh,
                           const float* __restrict__ hin, const int* upcnt,
                           float* __restrict__ rout, int* mycnt)
{
    __shared__ float sh_hin[4][HL];
    __shared__ float sh_xw[4][HR];
    __shared__ float sh_h[2][HR];
    const int tid = threadIdx.x;
    float wh[24], wi[48], bsum = 0.f;
    if (tid < 24) {
#pragma unroll
        for (int k = 0; k < 24; k++) wh[k] = Whh[tid * HR + k];
        sh_h[1][tid] = 0.f;
    }
    if (tid >= 32 && tid < 56) {
        int j = tid - 32;
#pragma unroll
        for (int k = 0; k < 48; k++) wi[k] = Wih[j * HL + k];
        bsum = bih[j] + bhh[j];
    }
    int avail = 0;
    if (tid >= 96) {
        int lane = tid - 96;
        for (int ft = 0; ft < 2; ft++) {
            while (avail < ft + 1) avail = ld_acq(upcnt);
            const float* src = hin + (size_t)ft * HL;
            sh_hin[ft][lane] = src[lane];
            if (lane < 16) sh_hin[ft][32 + lane] = src[32 + lane];
        }
    }
    __syncthreads();
    if (tid >= 32 && tid < 56) {
        float acc = bsum;
#pragma unroll
        for (int k = 0; k < 48; k++) acc += sh_hin[0][k] * wi[k];
        sh_xw[0][tid - 32] = acc;
    }
    __syncthreads();
    for (int t = 0; t < S_LEN; t++) {
        if (tid < 24) {
            float acc = sh_xw[t & 3][tid];
            const float* hp = sh_h[(t + 1) & 1];
#pragma unroll
            for (int k = 0; k < 24; k++) acc += hp[k] * wh[k];
            float h = actf(acc, 2.f);
            sh_h[t & 1][tid] = h;
            rout[(size_t)t * HR + tid] = h;
        } else if (tid >= 32 && tid < 56) {
            int tt = t + 1;
            if (tt < S_LEN) {
                float acc = bsum;
                const float* hs = sh_hin[tt & 3];
#pragma unroll
                for (int k = 0; k < 48; k++) acc += hs[k] * wi[k];
                sh_xw[tt & 3][tid - 32] = acc;
            }
        } else if (tid >= 96) {
            int lane = tid - 96, ft = t + 2;
            if (ft < S_LEN) {
                while (avail < ft + 1) avail = ld_acq(upcnt);
                const float* src = hin + (size_t)ft * HL;
                sh_hin[ft & 3][lane] = src[lane];
                if (lane < 16) sh_hin[ft & 3][32 + lane] = src[32 + lane];
            }
        }
        __syncthreads();
        if (tid == 0) st_rel(mycnt, t + 1);
    }
}

// ---------------- RNN1 + relu + fc4 -> out ----------------
__device__ void rnn1_stage(const float* __restrict__ Wih, const float* __restrict__ Whh,
                           const float* __restrict__ bih, const float* __restrict__ bhh,
                           const float* __restrict__ rin, const int* upcnt,
                           const float* __restrict__ fc4W, const float* __restrict__ fc4b,
                           float* __restrict__ out)
{
    __shared__ float sh_rin[4][HR];
    __shared__ float sh_xw[4][HR];
    __shared__ float sh_h[2][HR];
    __shared__ float sh_hr[2][HR];
    const int tid = threadIdx.x;
    float wh[24], wi[24], wf[24], bsum = 0.f, bf = 0.f;
    if (tid < 24) {
#pragma unroll
        for (int k = 0; k < 24; k++) wh[k] = Whh[tid * HR + k];
        sh_h[1][tid] = 0.f;
    }
    if (tid >= 32 && tid < 56) {
        int j = tid - 32;
#pragma unroll
        for (int k = 0; k < 24; k++) wi[k] = Wih[j * HR + k];
        bsum = bih[j] + bhh[j];
    }
    if (tid == 64 || tid == 65) {
        int o = tid - 64;
#pragma unroll
        for (int k = 0; k < 24; k++) wf[k] = fc4W[o * HR + k];
        bf = fc4b[o];
    }
    int avail = 0;
    if (tid >= 96) {
        int lane = tid - 96;
        for (int ft = 0; ft < 2; ft++) {
            while (avail < ft + 1) avail = ld_acq(upcnt);
            if (lane < 24) sh_rin[ft][lane] = rin[(size_t)ft * HR + lane];
        }
    }
    __syncthreads();
    if (tid >= 32 && tid < 56) {
        float acc = bsum;
#pragma unroll
        for (int k = 0; k < 24; k++) acc += sh_rin[0][k] * wi[k];
        sh_xw[0][tid - 32] = acc;
    }
    __syncthreads();
    for (int t = 0; t < S_LEN; t++) {
        if (tid < 24) {
            float acc = sh_xw[t & 3][tid];
            const float* hp = sh_h[(t + 1) & 1];
#pragma unroll
            for (int k = 0; k < 24; k++) acc += hp[k] * wh[k];
            float h = actf(acc, 2.f);
            sh_h[t & 1][tid] = h;
            sh_hr[t & 1][tid] = fmaxf(h, 0.f);
        } else if (tid >= 32 && tid < 56) {
            int tt = t + 1;
            if (tt < S_LEN) {
                float acc = bsum;
                const float* hs = sh_rin[tt & 3];
#pragma unroll
                for (int k = 0; k < 24; k++) acc += hs[k] * wi[k];
                sh_xw[tt & 3][tid - 32] = acc;
            }
        } else if (tid == 64 || tid == 65) {
            if (t > 0) {
                float acc = bf;
                const float* hr = sh_hr[(t - 1) & 1];
#pragma unroll
                for (int k = 0; k < 24; k++) acc += hr[k] * wf[k];
                out[(size_t)(t - 1) * 2 + (tid - 64)] = acc;
            }
        } else if (tid >= 96) {
            int lane = tid - 96, ft = t + 2;
            if (ft < S_LEN) {
                while (avail < ft + 1) avail = ld_acq(upcnt);
                if (lane < 24) sh_rin[ft & 3][lane] = rin[(size_t)ft * HR + lane];
            }
        }
        __syncthreads();
    }
    if (tid == 64 || tid == 65) {
        float acc = bf;
        const float* hr = sh_hr[(S_LEN - 1) & 1];
#pragma unroll
        for (int k = 0; k < 24; k++) acc += hr[k] * wf[k];
        out[(size_t)(S_LEN - 1) * 2 + (tid - 64)] = acc;
    }
}

// ---------------- pipeline dispatcher ----------------
__global__ void __launch_bounds__(128, 1) pipe_kernel(
    const float* lstm0_Whh,
    const float* lstmr_Wih, const float* lstmr_Whh,
    const float* lstmr_bih, const float* lstmr_bhh,
    const float* rnn0_Wih, const float* rnn0_Whh,
    const float* rnn0_bih, const float* rnn0_bhh,
    const float* rnn1_Wih, const float* rnn1_Whh,
    const float* rnn1_bih, const float* rnn1_bhh,
    const float* fc4W, const float* fc4b,
    float* out)
{
    const int b = blockIdx.x;
    if (b == 0) {
        lstm_rec(lstm0_Whh, g_xw0, 0, g_hb[0], &g_cnt[0]);
    } else if (b <= 8) {
        int l = (b - 1) / 2;           // lstmr layer 0..3
        if ((b & 1) == 1) {            // xw stage
            xw_stage(lstmr_Wih + (size_t)l * GATES * HL,
                     lstmr_bih + (size_t)l * GATES,
                     lstmr_bhh + (size_t)l * GATES,
                     g_hb[l], &g_cnt[2 * l], g_xwb[l], &g_cnt[2 * l + 1]);
        } else {                       // lstm recurrence
            lstm_rec(lstmr_Whh + (size_t)l * GATES * HL,
                     g_xwb[l], &g_cnt[2 * l + 1], g_hb[l + 1], &g_cnt[2 * l + 2]);
        }
    } else if (b == 9) {
        rnn0_stage(rnn0_Wih, rnn0_Whh, rnn0_bih, rnn0_bhh,
                   g_hb[4], &g_cnt[8], g_r0, &g_cnt[9]);
    } else {
        rnn1_stage(rnn1_Wih, rnn1_Whh, rnn1_bih, rnn1_bhh,
                   g_r0, &g_cnt[9], fc4W, fc4b, out);
    }
}

extern "C" void kernel_launch(void* const* d_in, const int* in_sizes, int n_in,
                              void* d_out, int out_size) {
    const float* x        = (const float*)d_in[0];
    const float* fc1_W    = (const float*)d_in[1];
    const float* fc1_b    = (const float*)d_in[2];
    const float* fc2_W    = (const float*)d_in[3];
    const float* fc2_b    = (const float*)d_in[4];
    const float* lstm0_Wih = (const float*)d_in[5];
    const float* lstm0_Whh = (const float*)d_in[6];
    const float* lstm0_bih = (const float*)d_in[7];
    const float* lstm0_bhh = (const float*)d_in[8];
    const float* lstmr_Wih = (const float*)d_in[9];
    const float* lstmr_Whh = (const float*)d_in[10];
    const float* lstmr_bih = (const float*)d_in[11];
    const float* lstmr_bhh = (const float*)d_in[12];
    const float* rnn0_Wih = (const float*)d_in[13];
    const float* rnn0_Whh = (const float*)d_in[14];
    const float* rnn0_bih = (const float*)d_in[15];
    const float* rnn0_bhh = (const float*)d_in[16];
    const float* rnn1_Wih = (const float*)d_in[17];
    const float* rnn1_Whh = (const float*)d_in[18];
    const float* rnn1_bih = (const float*)d_in[19];
    const float* rnn1_bhh = (const float*)d_in[20];
    const float* fc4_W    = (const float*)d_in[21];
    const float* fc4_b    = (const float*)d_in[22];
    float* out = (float*)d_out;

    front_kernel<<<S_LEN / 128, 128>>>(x, fc1_W, fc1_b, fc2_W, fc2_b,
                                       lstm0_Wih, lstm0_bih, lstm0_bhh);
    pipe_kernel<<<11, 128>>>(lstm0_Whh,
                             lstmr_Wih, lstmr_Whh, lstmr_bih, lstmr_bhh,
                             rnn0_Wih, rnn0_Whh, rnn0_bih, rnn0_bhh,
                             rnn1_Wih, rnn1_Whh, rnn1_bih, rnn1_bhh,
                             fc4_W, fc4_b, out);
}